// round 1
// baseline (speedup 1.0000x reference)
#include <cuda_runtime.h>

#define ND 768
#define SZ (768*768)      /* 589824 = M*N, also matrix element count */
#define MNTOT SZ

// ---------------- scratch (device globals; no allocations allowed) ----------
__device__ float g_T[2*5*SZ];   // [side][order][768*768]: side 0 = Tr, 1 = Tc
__device__ float g_Y[5*SZ];     // Y[0] holds copy of current x; Y[i]=Tr[i]@x
__device__ float g_bf[20*SZ];   // bf[i][j] for j=1..4 (j=0 aliases Y[i])
__device__ float g_xc[32*SZ];   // conv output, feature-major [o][r]
__device__ float g_h[32*SZ];    // LSTM hidden, feature-major
__device__ float g_c[32*SZ];    // LSTM cell, feature-major

struct SrcPtrs { const float* p[25]; };

// ---------------- identity fill ---------------------------------------------
__global__ __launch_bounds__(256) void eye_kernel(float* __restrict__ T) {
  int idx = blockIdx.x * 256 + threadIdx.x;
  if (idx < SZ) {
    int r = idx / ND;
    int cc = idx - r * ND;
    T[idx] = (r == cc) ? 1.0f : 0.0f;
  }
}

// ---------------- 128x128x8 SGEMM, batched via blockIdx.z -------------------
// C[z] = alpha * A[z] @ B[z] + beta-equivalent (Cin != nullptr -> + beta*Cin[z])
// offset(z) = s_z*z + s_div*(z/div) + s_mod*(z%div); A base selects A1 at z==1
__global__ __launch_bounds__(256) void sgemm_kernel(
    const float* __restrict__ A0, const float* __restrict__ A1,
    const float* __restrict__ B0, const float* __restrict__ Cin0,
    float* __restrict__ C0,
    long long sA_z, long long sA_div, long long sA_mod, int adiv,
    long long sB_z, long long sB_div, long long sB_mod, int bdiv,
    long long sCin_z, long long sC_z,
    float alpha, float beta)
{
  int z = blockIdx.z;
  const float* A = ((A1 != nullptr && z == 1) ? A1 : A0)
                   + sA_z * z + sA_div * (z / adiv) + sA_mod * (z % adiv);
  const float* B = B0 + sB_z * z + sB_div * (z / bdiv) + sB_mod * (z % bdiv);
  float* C = C0 + sC_z * z;
  const float* Cin = Cin0 ? (Cin0 + sCin_z * z) : (const float*)0;

  __shared__ float As[8][128];
  __shared__ float Bs[8][128];

  int t = threadIdx.x;
  int brow = blockIdx.y * 128;
  int bcol = blockIdx.x * 128;
  int tx = t & 15;   // 16 col-threads
  int ty = t >> 4;   // 16 row-threads

  float acc[8][8];
#pragma unroll
  for (int i = 0; i < 8; i++)
#pragma unroll
    for (int j = 0; j < 8; j++) acc[i][j] = 0.0f;

  int la_r = t >> 1;          // 0..127
  int la_c = (t & 1) * 4;     // 0 or 4
  int lb_r = t >> 5;          // 0..7
  int lb_c = (t & 31) * 4;    // 0..124

  const float* Aptr = A + (size_t)(brow + la_r) * ND + la_c;
  const float* Bptr = B + (size_t)lb_r * ND + bcol + lb_c;

  for (int k0 = 0; k0 < ND; k0 += 8) {
    float4 av = *(const float4*)(Aptr + k0);
    As[la_c + 0][la_r] = av.x;
    As[la_c + 1][la_r] = av.y;
    As[la_c + 2][la_r] = av.z;
    As[la_c + 3][la_r] = av.w;
    *(float4*)&Bs[lb_r][lb_c] = *(const float4*)(Bptr + (size_t)k0 * ND);
    __syncthreads();
#pragma unroll
    for (int k = 0; k < 8; k++) {
      float a[8], b[8];
      *(float4*)(a)     = *(const float4*)&As[k][ty * 4];
      *(float4*)(a + 4) = *(const float4*)&As[k][64 + ty * 4];
      *(float4*)(b)     = *(const float4*)&Bs[k][tx * 4];
      *(float4*)(b + 4) = *(const float4*)&Bs[k][64 + tx * 4];
#pragma unroll
      for (int i = 0; i < 8; i++)
#pragma unroll
        for (int j = 0; j < 8; j++) acc[i][j] += a[i] * b[j];
    }
    __syncthreads();
  }

#pragma unroll
  for (int i = 0; i < 8; i++) {
    int row = brow + ((i < 4) ? (ty * 4 + i) : (64 + ty * 4 + i - 4));
#pragma unroll
    for (int jh = 0; jh < 2; jh++) {
      int col = bcol + jh * 64 + tx * 4;
      float4 v;
      v.x = alpha * acc[i][jh * 4 + 0];
      v.y = alpha * acc[i][jh * 4 + 1];
      v.z = alpha * acc[i][jh * 4 + 2];
      v.w = alpha * acc[i][jh * 4 + 3];
      if (Cin) {
        float4 ci = *(const float4*)&Cin[(size_t)row * ND + col];
        v.x += beta * ci.x; v.y += beta * ci.y;
        v.z += beta * ci.z; v.w += beta * ci.w;
      }
      *(float4*)&C[(size_t)row * ND + col] = v;
    }
  }
}

// ---------------- theta contraction: xc[o][r] = sum_ij theta[i,j,o]*src[ij][r] + bias[o]
__global__ __launch_bounds__(256) void combine_kernel(
    SrcPtrs srcs, const float* __restrict__ theta, const float* __restrict__ bias,
    float* __restrict__ xc)
{
  __shared__ float th[800];
  __shared__ float bs[32];
  int t = threadIdx.x;
  for (int i = t; i < 800; i += 256) th[i] = theta[i];
  if (t < 32) bs[t] = bias[t];
  __syncthreads();

  size_t r = (size_t)blockIdx.x * 256 + t;
  float out[32];
#pragma unroll
  for (int o = 0; o < 32; o++) out[o] = bs[o];
#pragma unroll
  for (int ij = 0; ij < 25; ij++) {
    float v = __ldg(srcs.p[ij] + r);
    const float* tw = &th[ij * 32];
#pragma unroll
    for (int o = 0; o < 32; o++) out[o] += v * tw[o];
  }
#pragma unroll
  for (int o = 0; o < 32; o++) xc[(size_t)o * MNTOT + r] = out[o];
}

// ---------------- LSTM gates (K=32 GEMM, fused elementwise epilogue) --------
__device__ __forceinline__ float sigf(float v) {
  return __fdividef(1.0f, 1.0f + __expf(-v));
}

__global__ __launch_bounds__(256) void gates_kernel(
    const float* __restrict__ xc, float* h, float* c,
    const float* __restrict__ Wf, const float* __restrict__ Uf, const float* __restrict__ bf_,
    const float* __restrict__ Wi, const float* __restrict__ Ui, const float* __restrict__ bi_,
    const float* __restrict__ Wo, const float* __restrict__ Uo, const float* __restrict__ bo_,
    const float* __restrict__ Wc, const float* __restrict__ Uc, const float* __restrict__ bc_)
{
  __shared__ float sW[32][4][32];   // [k][gate][o]
  __shared__ float sU[32][4][32];
  __shared__ float sb[4][32];
  int t = threadIdx.x;
  {
    const float* Ws[4] = {Wf, Wi, Wo, Wc};
    const float* Us[4] = {Uf, Ui, Uo, Uc};
    for (int idx = t; idx < 4096; idx += 256) {
      int k = idx >> 7;
      int g = (idx >> 5) & 3;
      int o = idx & 31;
      sW[k][g][o] = Ws[g][k * 32 + o];
      sU[k][g][o] = Us[g][k * 32 + o];
    }
    if (t < 128) {
      const float* bsx[4] = {bf_, bi_, bo_, bc_};
      sb[t >> 5][t & 31] = bsx[t >> 5][t & 31];
    }
  }
  __syncthreads();

  int rt = t & 31;                       // 32 r-threads x 4 r each = 128 r/block
  int ot = t >> 5;                       // 8 o-threads x 4 o each = 32 o
  size_t r0 = (size_t)blockIdx.x * 128 + rt * 4;
  int ob = ot * 4;

  float acc[4][4][4];                    // [o][gate][r]
#pragma unroll
  for (int o = 0; o < 4; o++)
#pragma unroll
    for (int g = 0; g < 4; g++)
#pragma unroll
      for (int rr = 0; rr < 4; rr++) acc[o][g][rr] = 0.0f;

#pragma unroll 4
  for (int k = 0; k < 32; k++) {
    float4 xv = *(const float4*)&xc[(size_t)k * MNTOT + r0];
    float4 hv = *(const float4*)&h[(size_t)k * MNTOT + r0];
    float xr[4] = {xv.x, xv.y, xv.z, xv.w};
    float hr[4] = {hv.x, hv.y, hv.z, hv.w};
#pragma unroll
    for (int g = 0; g < 4; g++) {
      float4 w4 = *(const float4*)&sW[k][g][ob];
      float4 u4 = *(const float4*)&sU[k][g][ob];
      float w[4] = {w4.x, w4.y, w4.z, w4.w};
      float u[4] = {u4.x, u4.y, u4.z, u4.w};
#pragma unroll
      for (int o = 0; o < 4; o++)
#pragma unroll
        for (int rr = 0; rr < 4; rr++)
          acc[o][g][rr] += w[o] * xr[rr] + u[o] * hr[rr];
    }
  }
  __syncthreads();   // all h reads done before any h writes (in-place update)

#pragma unroll
  for (int o = 0; o < 4; o++) {
    int oo = ob + o;
    float4 c4 = *(const float4*)&c[(size_t)oo * MNTOT + r0];
    float co[4] = {c4.x, c4.y, c4.z, c4.w};
    float cn[4], hn[4];
#pragma unroll
    for (int rr = 0; rr < 4; rr++) {
      float fg = sigf(acc[o][0][rr] + sb[0][oo]);
      float ig = sigf(acc[o][1][rr] + sb[1][oo]);
      float og = sigf(acc[o][2][rr] + sb[2][oo]);
      float cu = sigf(acc[o][3][rr] + sb[3][oo]);   // sigmoid, per source
      float cnew = fg * co[rr] + ig * cu;
      cn[rr] = cnew;
      hn[rr] = og * sigf(cnew);                      // h = o * sigmoid(c)
    }
    float4 cv; cv.x = cn[0]; cv.y = cn[1]; cv.z = cn[2]; cv.w = cn[3];
    float4 hv2; hv2.x = hn[0]; hv2.y = hn[1]; hv2.z = hn[2]; hv2.w = hn[3];
    *(float4*)&c[(size_t)oo * MNTOT + r0] = cv;
    *(float4*)&h[(size_t)oo * MNTOT + r0] = hv2;
  }
}

// ---------------- dx = tanh(c @ W_out + b_out), x += dx ---------------------
__global__ __launch_bounds__(256) void dx_kernel(
    const float* __restrict__ c, const float* __restrict__ Wout,
    const float* __restrict__ bout, float* __restrict__ x)
{
  __shared__ float sw[32];
  __shared__ float sb0;
  int t = threadIdx.x;
  if (t < 32) sw[t] = Wout[t];
  if (t == 0) sb0 = bout[0];
  __syncthreads();
  size_t r = (size_t)blockIdx.x * 256 + t;
  float acc = sb0;
#pragma unroll
  for (int o = 0; o < 32; o++) acc += c[(size_t)o * MNTOT + r] * sw[o];
  x[r] += tanhf(acc);
}

// ---------------- orchestration ---------------------------------------------
extern "C" void kernel_launch(void* const* d_in, const int* in_sizes, int n_in,
                              void* d_out, int out_size)
{
  const float* x     = (const float*)d_in[0];
  const float* L_row = (const float*)d_in[1];
  const float* L_col = (const float*)d_in[2];
  const float* theta = (const float*)d_in[3];
  const float* bias  = (const float*)d_in[4];
  const float* W_f = (const float*)d_in[5];
  const float* U_f = (const float*)d_in[6];
  const float* b_f = (const float*)d_in[7];
  const float* W_i = (const float*)d_in[8];
  const float* U_i = (const float*)d_in[9];
  const float* b_i = (const float*)d_in[10];
  const float* W_o = (const float*)d_in[11];
  const float* U_o = (const float*)d_in[12];
  const float* b_o = (const float*)d_in[13];
  const float* W_c = (const float*)d_in[14];
  const float* U_c = (const float*)d_in[15];
  const float* b_c = (const float*)d_in[16];
  const float* W_out = (const float*)d_in[17];
  const float* b_out = (const float*)d_in[18];
  // d_in[19] = nb_iterations_rnn, fixed at 3 by the problem setup

  float* xcur = (float*)d_out;
  float *T, *Y, *bfm, *xcb, *h, *c;
  cudaGetSymbolAddress((void**)&T,   g_T);
  cudaGetSymbolAddress((void**)&Y,   g_Y);
  cudaGetSymbolAddress((void**)&bfm, g_bf);
  cudaGetSymbolAddress((void**)&xcb, g_xc);
  cudaGetSymbolAddress((void**)&h,   g_h);
  cudaGetSymbolAddress((void**)&c,   g_c);

  const long long S = SZ;
  float* Tr = T;
  float* Tc = T + 5 * S;

  cudaMemcpyAsync(xcur, x, SZ * sizeof(float), cudaMemcpyDeviceToDevice);
  eye_kernel<<<SZ / 256, 256>>>(Tr);
  eye_kernel<<<SZ / 256, 256>>>(Tc);
  cudaMemcpyAsync(Tr + S, L_row, SZ * sizeof(float), cudaMemcpyDeviceToDevice);
  cudaMemcpyAsync(Tc + S, L_col, SZ * sizeof(float), cudaMemcpyDeviceToDevice);

  // Chebyshev recursion: T_k = 2*L@T_{k-1} - T_{k-2}; z=0 row chain, z=1 col chain
  for (int k = 2; k <= 4; k++) {
    dim3 g(6, 6, 2);
    sgemm_kernel<<<g, 256>>>(L_row, L_col,
        T + (long long)(k - 1) * S,          // B base
        T + (long long)(k - 2) * S,          // Cin base
        T + (long long)k * S,                // C base
        0, 0, 0, 1,                          // A offsets (pure A0/A1 select)
        5 * S, 0, 0, 1,                      // B: +5S per side
        5 * S, 5 * S,                        // Cin, C: +5S per side
        2.0f, -1.0f);
  }

  cudaMemsetAsync(h, 0, (size_t)32 * SZ * sizeof(float));
  cudaMemsetAsync(c, 0, (size_t)32 * SZ * sizeof(float));

  SrcPtrs sp;
  for (int i = 0; i < 5; i++)
    for (int j = 0; j < 5; j++)
      sp.p[i * 5 + j] = (j == 0) ? (Y + (long long)i * S)
                                 : (bfm + (long long)(i * 4 + j - 1) * S);

  for (int it = 0; it < 3; it++) {
    // Y[0] = current x (so Y_i arithmetic is uniform; Tr[0]=I needs no GEMM)
    cudaMemcpyAsync(Y, xcur, SZ * sizeof(float), cudaMemcpyDeviceToDevice);

    // Y[1..4] = Tr[1..4] @ x     (z = 0..3)
    {
      dim3 g(6, 6, 4);
      sgemm_kernel<<<g, 256>>>(Tr + S, nullptr, Y, nullptr, Y + S,
          S, 0, 0, 1,    0, 0, 0, 1,    0, S, 1.0f, 0.0f);
    }
    // bf[i][j] = Y[i] @ Tc[j], i=0..4, j=1..4  (z = i*4 + (j-1), 20 GEMMs)
    {
      dim3 g(6, 6, 20);
      sgemm_kernel<<<g, 256>>>(Y, nullptr, Tc + S, nullptr, bfm,
          0, S, 0, 4,    0, 0, S, 4,    0, S, 1.0f, 0.0f);
    }
    combine_kernel<<<SZ / 256, 256>>>(sp, theta, bias, xcb);
    gates_kernel<<<SZ / 128, 256>>>(xcb, h, c,
        W_f, U_f, b_f, W_i, U_i, b_i, W_o, U_o, b_o, W_c, U_c, b_c);
    dx_kernel<<<SZ / 256, 256>>>(c, W_out, b_out, xcur);
  }
}

// round 3
// speedup vs baseline: 1.7769x; 1.7769x over previous
#include <cuda_runtime.h>
#include <cuda_bf16.h>
#include <cstdint>

#define ND 768
#define SZ (768*768)
#define MNTOT SZ
typedef long long ll;

// ---------------- scratch (device globals) ----------------------------------
__device__ float g_Tf[10*SZ];                         // fp32 T[side][k]
__device__ __align__(16) __nv_bfloat16 g_Tsh[10*SZ];  // split hi
__device__ __align__(16) __nv_bfloat16 g_Tsl[10*SZ];  // split lo
__device__ __align__(16) __nv_bfloat16 g_xTh[SZ];
__device__ __align__(16) __nv_bfloat16 g_xTl[SZ];
__device__ float g_Yf[4*SZ];                          // Y_1..Y_4 fp32
__device__ __align__(16) __nv_bfloat16 g_Ysh[5*SZ];   // Y_0..Y_4 split
__device__ __align__(16) __nv_bfloat16 g_Ysl[5*SZ];
__device__ float g_bff[20*SZ];
__device__ float g_xc[32*SZ];
__device__ float g_h[32*SZ];
__device__ float g_c[32*SZ];

struct SrcPtrs { const float* p[25]; };

// ---------------- helpers -----------------------------------------------------
#define SWZ(x) ((x) ^ (((x) >> 3) & 0x70))

__device__ __forceinline__ uint32_t smem_u32(const void* p) {
  uint32_t a;
  asm("{ .reg .u64 t; cvta.to.shared.u64 t, %1; cvt.u32.u64 %0, t; }"
      : "=r"(a) : "l"(p));
  return a;
}

__device__ __forceinline__ void cpa16(uint32_t dst, const void* src) {
  asm volatile("cp.async.cg.shared.global [%0], [%1], 16;"
               :: "r"(dst), "l"(src) : "memory");
}
#define CP_COMMIT() asm volatile("cp.async.commit_group;" ::: "memory")
#define CP_WAIT(n)  asm volatile("cp.async.wait_group %0;" :: "n"(n) : "memory")

__device__ __forceinline__ void ldm4(uint32_t* r, uint32_t addr) {
  asm volatile("ldmatrix.sync.aligned.m8n8.x4.shared.b16 {%0,%1,%2,%3}, [%4];"
               : "=r"(r[0]), "=r"(r[1]), "=r"(r[2]), "=r"(r[3]) : "r"(addr));
}

__device__ __forceinline__ void mma16816(float* c, const uint32_t* a,
                                         const uint32_t* b) {
  asm volatile(
      "mma.sync.aligned.m16n8k16.row.col.f32.bf16.bf16.f32 "
      "{%0,%1,%2,%3},{%4,%5,%6,%7},{%8,%9},{%0,%1,%2,%3};"
      : "+f"(c[0]), "+f"(c[1]), "+f"(c[2]), "+f"(c[3])
      : "r"(a[0]), "r"(a[1]), "r"(a[2]), "r"(a[3]), "r"(b[0]), "r"(b[1]));
}

// load one 64-wide K chunk of 4 matrices (Ah,Al,Bh,Bl) via cp.async
// tile layout per matrix: 128 rows x 128 bytes (64 bf16), SW128 swizzled
__device__ __forceinline__ void load_chunk(
    uint32_t sb, int s, int kc, int tid, int brow, int bcol,
    const __nv_bfloat16* a0, const __nv_bfloat16* a1,
    const __nv_bfloat16* b0, const __nv_bfloat16* b1)
{
  const __nv_bfloat16* srcs[4] = {a0, a1, b0, b1};
#pragma unroll
  for (int i = 0; i < 16; i++) {
    int idx = tid + i * 256;
    int mat = idx >> 10;            // constant per i after unroll
    int row = (idx >> 3) & 127;
    int c4  = idx & 7;
    int rb  = (mat < 2) ? brow : bcol;
    const __nv_bfloat16* src = srcs[mat] + (ll)(rb + row) * ND + kc * 64 + c4 * 8;
    cpa16(sb + s * 65536 + mat * 16384 + SWZ(row * 128 + c4 * 16), src);
  }
}

// ---------------- tensor-core GEMM: C = alpha*A@B~^T + beta*Cin --------------
// A,B fp32-as-split-bf16 (hi+lo). B~ is [N,K] K-major (pass B^T; symmetric ops
// pass B). offA = sAz*z + sAdiv*(z/adiv); offB = sBz*z + sBmod*(z%bmod)
// cinmode: 0 none, 1 identity (+beta on diagonal), 2 pointer
__global__ __launch_bounds__(256, 1) void tc_gemm(
    const __nv_bfloat16* __restrict__ Ah, const __nv_bfloat16* __restrict__ Al,
    const __nv_bfloat16* __restrict__ Bh, const __nv_bfloat16* __restrict__ Bl,
    const float* __restrict__ Cin, float* __restrict__ Cout,
    ll sAz, ll sAdiv, int adiv,
    ll sBz, ll sBmod, int bmod,
    ll sCinz, ll sCz, float alpha, float beta, int cinmode)
{
  extern __shared__ char dsm[];

  int z = blockIdx.z;
  ll offA = sAz * z + sAdiv * (z / adiv);
  ll offB = sBz * z + sBmod * (z % bmod);
  const __nv_bfloat16* ah = Ah + offA;
  const __nv_bfloat16* al = Al + offA;
  const __nv_bfloat16* bh = Bh + offB;
  const __nv_bfloat16* bl = Bl + offB;
  const int brow = blockIdx.y * 128;
  const int bcol = blockIdx.x * 128;

  int tid = threadIdx.x;
  int lane = tid & 31;
  int wid = tid >> 5;
  int wrow = (wid & 3) * 32;   // warp M offset within tile
  int wcol = (wid >> 2) * 64;  // warp N offset within tile

  uint32_t raw = smem_u32(dsm);
  uint32_t sb = (raw + 1023) & ~1023u;   // 1024-aligned tile area (128 KB)

  float acc[2][8][4];
#pragma unroll
  for (int mi = 0; mi < 2; mi++)
#pragma unroll
    for (int ni = 0; ni < 8; ni++)
#pragma unroll
      for (int e = 0; e < 4; e++) acc[mi][ni][e] = 0.0f;

  // per-lane ldmatrix address components (within a 128x128B tile)
  int a_r  = (lane & 7) + ((lane >> 3) & 1) * 8;  // m within m16
  int a_k8 = ((lane >> 4) & 1) * 8;               // k8 half
  int b_r  = (lane & 7) + ((lane >> 4) & 1) * 8;  // n within n16
  int b_k8 = ((lane >> 3) & 1) * 8;

  load_chunk(sb, 0, 0, tid, brow, bcol, ah, al, bh, bl); CP_COMMIT();
  load_chunk(sb, 1, 1, tid, brow, bcol, ah, al, bh, bl); CP_COMMIT();

  for (int kc = 0; kc < 12; kc++) {
    if (kc < 11) { CP_WAIT(1); } else { CP_WAIT(0); }
    __syncthreads();

    uint32_t tAh = sb + (kc & 1) * 65536;
    uint32_t tAl = tAh + 16384;
    uint32_t tBh = tAh + 32768;
    uint32_t tBl = tAh + 49152;

#pragma unroll
    for (int s = 0; s < 4; s++) {
      uint32_t fah[2][4], fal[2][4];
#pragma unroll
      for (int mi = 0; mi < 2; mi++) {
        int r = wrow + mi * 16 + a_r;
        uint32_t off = SWZ(r * 128 + (s * 16 + a_k8) * 2);
        ldm4(fah[mi], tAh + off);
        ldm4(fal[mi], tAl + off);
      }
      uint32_t fbh[8][2], fbl[8][2];
#pragma unroll
      for (int nj = 0; nj < 4; nj++) {
        int r = wcol + nj * 16 + b_r;
        uint32_t off = SWZ(r * 128 + (s * 16 + b_k8) * 2);
        uint32_t t4[4];
        ldm4(t4, tBh + off);
        fbh[nj * 2][0] = t4[0]; fbh[nj * 2][1] = t4[1];
        fbh[nj * 2 + 1][0] = t4[2]; fbh[nj * 2 + 1][1] = t4[3];
        ldm4(t4, tBl + off);
        fbl[nj * 2][0] = t4[0]; fbl[nj * 2][1] = t4[1];
        fbl[nj * 2 + 1][0] = t4[2]; fbl[nj * 2 + 1][1] = t4[3];
      }
#pragma unroll
      for (int mi = 0; mi < 2; mi++)
#pragma unroll
        for (int ni = 0; ni < 8; ni++)
          mma16816(acc[mi][ni], fah[mi], fbh[ni]);
#pragma unroll
      for (int mi = 0; mi < 2; mi++)
#pragma unroll
        for (int ni = 0; ni < 8; ni++)
          mma16816(acc[mi][ni], fah[mi], fbl[ni]);
#pragma unroll
      for (int mi = 0; mi < 2; mi++)
#pragma unroll
        for (int ni = 0; ni < 8; ni++)
          mma16816(acc[mi][ni], fal[mi], fbh[ni]);
    }

    __syncthreads();   // all warps done reading before refill
    if (kc + 2 < 12) {
      load_chunk(sb, kc & 1, kc + 2, tid, brow, bcol, ah, al, bh, bl);
      CP_COMMIT();
    }
  }

  // ---- epilogue: registers -> gmem (float2 per fragment half) ---------------
  const float* cinp = (cinmode == 2) ? (Cin + sCinz * z) : (const float*)0;
  float* co = Cout + sCz * z;
  int qr = lane >> 2, qc = lane & 3;

#pragma unroll
  for (int mi = 0; mi < 2; mi++) {
#pragma unroll
    for (int ni = 0; ni < 8; ni++) {
      int gr0 = brow + wrow + mi * 16 + qr;
      int gc  = bcol + wcol + ni * 8 + qc * 2;
      float2 v0, v1;
      v0.x = alpha * acc[mi][ni][0];
      v0.y = alpha * acc[mi][ni][1];
      v1.x = alpha * acc[mi][ni][2];
      v1.y = alpha * acc[mi][ni][3];
      if (cinmode == 2) {
        float2 c0 = *(const float2*)&cinp[(ll)gr0 * ND + gc];
        float2 c1 = *(const float2*)&cinp[(ll)(gr0 + 8) * ND + gc];
        v0.x += beta * c0.x; v0.y += beta * c0.y;
        v1.x += beta * c1.x; v1.y += beta * c1.y;
      } else if (cinmode == 1) {
        if (gr0 == gc)         v0.x += beta;
        if (gr0 == gc + 1)     v0.y += beta;
        if (gr0 + 8 == gc)     v1.x += beta;
        if (gr0 + 8 == gc + 1) v1.y += beta;
      }
      *(float2*)&co[(ll)gr0 * ND + gc]       = v0;
      *(float2*)&co[(ll)(gr0 + 8) * ND + gc] = v1;
    }
  }
}

// ---------------- fp32 -> split bf16 -----------------------------------------
__device__ __forceinline__ uint32_t pack2(__nv_bfloat16 a, __nv_bfloat16 b) {
  __nv_bfloat162 t(a, b);
  return *reinterpret_cast<uint32_t*>(&t);
}

__global__ __launch_bounds__(256) void split_kernel(
    const float* __restrict__ src, __nv_bfloat16* __restrict__ hi,
    __nv_bfloat16* __restrict__ lo, ll sS, ll sD)
{
  ll so = sS * blockIdx.z, dofs = sD * blockIdx.z;
  int idx = blockIdx.x * 256 + threadIdx.x;   // over SZ/4
  float4 v = *(const float4*)(src + so + (ll)idx * 4);
  float a[4] = {v.x, v.y, v.z, v.w};
  __nv_bfloat16 h[4], l[4];
#pragma unroll
  for (int e = 0; e < 4; e++) {
    h[e] = __float2bfloat16(a[e]);
    l[e] = __float2bfloat16(a[e] - __bfloat162float(h[e]));
  }
  uint2 uh, ul;
  uh.x = pack2(h[0], h[1]); uh.y = pack2(h[2], h[3]);
  ul.x = pack2(l[0], l[1]); ul.y = pack2(l[2], l[3]);
  *(uint2*)(hi + dofs + (ll)idx * 4) = uh;
  *(uint2*)(lo + dofs + (ll)idx * 4) = ul;
}

// ---------------- transpose + split: xT = x^T --------------------------------
__global__ void tsplit_kernel(const float* __restrict__ src,
                              __nv_bfloat16* __restrict__ th,
                              __nv_bfloat16* __restrict__ tl)
{
  __shared__ float t[32][33];
  int bx = blockIdx.x * 32, by = blockIdx.y * 32;
  int tx = threadIdx.x, ty = threadIdx.y;   // 32 x 8
#pragma unroll
  for (int i = 0; i < 4; i++)
    t[ty + 8 * i][tx] = src[(ll)(by + ty + 8 * i) * ND + bx + tx];
  __syncthreads();
#pragma unroll
  for (int i = 0; i < 4; i++) {
    float a = t[tx][ty + 8 * i];
    __nv_bfloat16 h = __float2bfloat16(a);
    __nv_bfloat16 l = __float2bfloat16(a - __bfloat162float(h));
    ll o = (ll)(bx + ty + 8 * i) * ND + by + tx;
    th[o] = h;
    tl[o] = l;
  }
}

// ---------------- theta contraction ------------------------------------------
__global__ __launch_bounds__(256) void combine_kernel(
    SrcPtrs srcs, const float* __restrict__ theta, const float* __restrict__ bias,
    float* __restrict__ xc)
{
  __shared__ float th[800];
  __shared__ float bs[32];
  int t = threadIdx.x;
  for (int i = t; i < 800; i += 256) th[i] = theta[i];
  if (t < 32) bs[t] = bias[t];
  __syncthreads();

  size_t r = (size_t)blockIdx.x * 256 + t;
  float out[32];
#pragma unroll
  for (int o = 0; o < 32; o++) out[o] = bs[o];
#pragma unroll
  for (int ij = 0; ij < 25; ij++) {
    float v = __ldg(srcs.p[ij] + r);
    const float* tw = &th[ij * 32];
#pragma unroll
    for (int o = 0; o < 32; o++) out[o] += v * tw[o];
  }
#pragma unroll
  for (int o = 0; o < 32; o++) xc[(size_t)o * MNTOT + r] = out[o];
}

// ---------------- LSTM gates --------------------------------------------------
__device__ __forceinline__ float sigf(float v) {
  return __fdividef(1.0f, 1.0f + __expf(-v));
}

__global__ __launch_bounds__(256) void gates_kernel(
    const float* __restrict__ xc, float* h, float* c,
    const float* __restrict__ Wf, const float* __restrict__ Uf, const float* __restrict__ bf_,
    const float* __restrict__ Wi, const float* __restrict__ Ui, const float* __restrict__ bi_,
    const float* __restrict__ Wo, const float* __restrict__ Uo, const float* __restrict__ bo_,
    const float* __restrict__ Wc, const float* __restrict__ Uc, const float* __restrict__ bc_)
{
  __shared__ float sW[32][4][32];
  __shared__ float sU[32][4][32];
  __shared__ float sb[4][32];
  int t = threadIdx.x;
  {
    const float* Ws[4] = {Wf, Wi, Wo, Wc};
    const float* Us[4] = {Uf, Ui, Uo, Uc};
    for (int idx = t; idx < 4096; idx += 256) {
      int k = idx >> 7;
      int g = (idx >> 5) & 3;
      int o = idx & 31;
      sW[k][g][o] = Ws[g][k * 32 + o];
      sU[k][g][o] = Us[g][k * 32 + o];
    }
    if (t < 128) {
      const float* bsx[4] = {bf_, bi_, bo_, bc_};
      sb[t >> 5][t & 31] = bsx[t >> 5][t & 31];
    }
  }
  __syncthreads();

  int rt = t & 31;
  int ot = t >> 5;
  size_t r0 = (size_t)blockIdx.x * 128 + rt * 4;
  int ob = ot * 4;

  float acc[4][4][4];
#pragma unroll
  for (int o = 0; o < 4; o++)
#pragma unroll
    for (int g = 0; g < 4; g++)
#pragma unroll
      for (int rr = 0; rr < 4; rr++) acc[o][g][rr] = 0.0f;

#pragma unroll 4
  for (int k = 0; k < 32; k++) {
    float4 xv = *(const float4*)&xc[(size_t)k * MNTOT + r0];
    float4 hv = *(const float4*)&h[(size_t)k * MNTOT + r0];
    float xr[4] = {xv.x, xv.y, xv.z, xv.w};
    float hr[4] = {hv.x, hv.y, hv.z, hv.w};
#pragma unroll
    for (int g = 0; g < 4; g++) {
      float4 w4 = *(const float4*)&sW[k][g][ob];
      float4 u4 = *(const float4*)&sU[k][g][ob];
      float w[4] = {w4.x, w4.y, w4.z, w4.w};
      float u[4] = {u4.x, u4.y, u4.z, u4.w};
#pragma unroll
      for (int o = 0; o < 4; o++)
#pragma unroll
        for (int rr = 0; rr < 4; rr++)
          acc[o][g][rr] += w[o] * xr[rr] + u[o] * hr[rr];
    }
  }
  __syncthreads();

#pragma unroll
  for (int o = 0; o < 4; o++) {
    int oo = ob + o;
    float4 c4 = *(const float4*)&c[(size_t)oo * MNTOT + r0];
    float co[4] = {c4.x, c4.y, c4.z, c4.w};
    float cn[4], hn[4];
#pragma unroll
    for (int rr = 0; rr < 4; rr++) {
      float fg = sigf(acc[o][0][rr] + sb[0][oo]);
      float ig = sigf(acc[o][1][rr] + sb[1][oo]);
      float og = sigf(acc[o][2][rr] + sb[2][oo]);
      float cu = sigf(acc[o][3][rr] + sb[3][oo]);
      float cnew = fg * co[rr] + ig * cu;
      cn[rr] = cnew;
      hn[rr] = og * sigf(cnew);
    }
    float4 cv; cv.x = cn[0]; cv.y = cn[1]; cv.z = cn[2]; cv.w = cn[3];
    float4 hv2; hv2.x = hn[0]; hv2.y = hn[1]; hv2.z = hn[2]; hv2.w = hn[3];
    *(float4*)&c[(size_t)oo * MNTOT + r0] = cv;
    *(float4*)&h[(size_t)oo * MNTOT + r0] = hv2;
  }
}

// ---------------- dx = tanh(c @ W_out + b_out); x += dx ----------------------
__global__ __launch_bounds__(256) void dx_kernel(
    const float* __restrict__ c, const float* __restrict__ Wout,
    const float* __restrict__ bout, float* __restrict__ x)
{
  __shared__ float sw[32];
  __shared__ float sb0;
  int t = threadIdx.x;
  if (t < 32) sw[t] = Wout[t];
  if (t == 0) sb0 = bout[0];
  __syncthreads();
  size_t r = (size_t)blockIdx.x * 256 + t;
  float acc = sb0;
#pragma unroll
  for (int o = 0; o < 32; o++) acc += c[(size_t)o * MNTOT + r] * sw[o];
  x[r] += tanhf(acc);
}

// ---------------- orchestration ----------------------------------------------
extern "C" void kernel_launch(void* const* d_in, const int* in_sizes, int n_in,
                              void* d_out, int out_size)
{
  const float* x     = (const float*)d_in[0];
  const float* L_row = (const float*)d_in[1];
  const float* L_col = (const float*)d_in[2];
  const float* theta = (const float*)d_in[3];
  const float* bias  = (const float*)d_in[4];
  const float* W_f = (const float*)d_in[5];
  const float* U_f = (const float*)d_in[6];
  const float* b_f = (const float*)d_in[7];
  const float* W_i = (const float*)d_in[8];
  const float* U_i = (const float*)d_in[9];
  const float* b_i = (const float*)d_in[10];
  const float* W_o = (const float*)d_in[11];
  const float* U_o = (const float*)d_in[12];
  const float* b_o = (const float*)d_in[13];
  const float* W_c = (const float*)d_in[14];
  const float* U_c = (const float*)d_in[15];
  const float* b_c = (const float*)d_in[16];
  const float* W_out = (const float*)d_in[17];
  const float* b_out = (const float*)d_in[18];
  // d_in[19] = nb_iterations_rnn = 3 (fixed by setup)

  float* xcur = (float*)d_out;

  float *Tf, *Yf, *bff, *xcb, *h, *c;
  __nv_bfloat16 *Tsh, *Tsl, *xTh, *xTl, *Ysh, *Ysl;
  cudaGetSymbolAddress((void**)&Tf,  g_Tf);
  cudaGetSymbolAddress((void**)&Tsh, g_Tsh);
  cudaGetSymbolAddress((void**)&Tsl, g_Tsl);
  cudaGetSymbolAddress((void**)&xTh, g_xTh);
  cudaGetSymbolAddress((void**)&xTl, g_xTl);
  cudaGetSymbolAddress((void**)&Yf,  g_Yf);
  cudaGetSymbolAddress((void**)&Ysh, g_Ysh);
  cudaGetSymbolAddress((void**)&Ysl, g_Ysl);
  cudaGetSymbolAddress((void**)&bff, g_bff);
  cudaGetSymbolAddress((void**)&xcb, g_xc);
  cudaGetSymbolAddress((void**)&h,   g_h);
  cudaGetSymbolAddress((void**)&c,   g_c);

  const ll S = SZ;
  const int DSM = 1024 + 128 * 1024;   // align slack + 2 x 64KB stages
  cudaFuncSetAttribute(tc_gemm, cudaFuncAttributeMaxDynamicSharedMemorySize, DSM);

  cudaMemcpyAsync(xcur, x, SZ * sizeof(float), cudaMemcpyDeviceToDevice);
  // T[side][1] = L
  cudaMemcpyAsync(Tf + 1 * S, L_row, SZ * sizeof(float), cudaMemcpyDeviceToDevice);
  cudaMemcpyAsync(Tf + 6 * S, L_col, SZ * sizeof(float), cudaMemcpyDeviceToDevice);
  {
    dim3 g(SZ / 1024, 1, 2);
    split_kernel<<<g, 256>>>(Tf + S, Tsh + S, Tsl + S, 5 * S, 5 * S);
  }

  // Chebyshev: T_k = 2*L@T_{k-1} - T_{k-2} (all operands symmetric)
  for (int k = 2; k <= 4; k++) {
    dim3 g(6, 6, 2);
    int cinmode = (k == 2) ? 1 : 2;
    const float* cin = (k == 2) ? (const float*)0 : (Tf + (ll)(k - 2) * S);
    tc_gemm<<<g, 256, DSM>>>(
        Tsh + S, Tsl + S,                 // A = L split, z-stride 5S
        Tsh + (ll)(k - 1) * S, Tsl + (ll)(k - 1) * S,
        cin, Tf + (ll)k * S,
        5 * S, 0, 1,                      // A offsets
        5 * S, 0, 1,                      // B offsets
        5 * S, 5 * S, 2.0f, -1.0f, cinmode);
    dim3 gs(SZ / 1024, 1, 2);
    split_kernel<<<gs, 256>>>(Tf + (ll)k * S, Tsh + (ll)k * S, Tsl + (ll)k * S,
                              5 * S, 5 * S);
  }

  cudaMemsetAsync(h, 0, (size_t)32 * SZ * sizeof(float));
  cudaMemsetAsync(c, 0, (size_t)32 * SZ * sizeof(float));

  SrcPtrs sp;
  for (int i = 0; i < 5; i++)
    for (int j = 0; j < 5; j++)
      sp.p[i * 5 + j] = (j == 0)
          ? ((i == 0) ? (const float*)xcur : (Yf + (ll)(i - 1) * S))
          : (bff + (ll)(i * 4 + j - 1) * S);

  for (int it = 0; it < 3; it++) {
    // x^T split (B operand for Y-GEMM)
    {
      dim3 g(24, 24);
      dim3 b(32, 8);
      tsplit_kernel<<<g, b>>>(xcur, xTh, xTl);
    }
    // Ys[0] = split(x)
    {
      dim3 g(SZ / 1024, 1, 1);
      split_kernel<<<g, 256>>>(xcur, Ysh, Ysl, 0, 0);
    }
    // Y_z+1 = Tr_{1+z} @ x  (B~ = x^T), z = 0..3
    {
      dim3 g(6, 6, 4);
      tc_gemm<<<g, 256, DSM>>>(
          Tsh + S, Tsl + S, xTh, xTl,
          (const float*)0, Yf,
          S, 0, 1,    0, 0, 1,
          0, S, 1.0f, 0.0f, 0);
    }
    // split Y_1..4 -> Ys[1..4]
    {
      dim3 g(SZ / 1024, 1, 4);
      split_kernel<<<g, 256>>>(Yf, Ysh + S, Ysl + S, S, S);
    }
    // bf[z] = Y_{z/4} @ Tc_{1+z%4}  (B~ = Tc symmetric), z = 0..19
    {
      dim3 g(6, 6, 20);
      tc_gemm<<<g, 256, DSM>>>(
          Ysh, Ysl, Tsh + 6 * S, Tsl + 6 * S,
          (const float*)0, bff,
          0, S, 4,    0, S, 4,
          0, S, 1.0f, 0.0f, 0);
    }
    combine_kernel<<<SZ / 256, 256>>>(sp, theta, bias, xcb);
    gates_kernel<<<SZ / 128, 256>>>(xcb, h, c,
        W_f, U_f, b_f, W_i, U_i, b_i, W_o, U_o, b_o, W_c, U_c, b_c);
    dx_kernel<<<SZ / 256, 256>>>(c, W_out, b_out, xcur);
  }
}

// round 4
// speedup vs baseline: 1.9394x; 1.0915x over previous
#include <cuda_runtime.h>
#include <cuda_bf16.h>
#include <cstdint>

#define ND 768
#define SZ (768*768)
#define MNTOT SZ
typedef long long ll;

// ---------------- scratch (device globals) ----------------------------------
__device__ float g_Tf[10*SZ];                         // fp32 T[side][k]
__device__ __align__(16) __nv_bfloat16 g_Tsh[10*SZ];  // split hi
__device__ __align__(16) __nv_bfloat16 g_Tsl[10*SZ];  // split lo
__device__ __align__(16) __nv_bfloat16 g_xTh[SZ];
__device__ __align__(16) __nv_bfloat16 g_xTl[SZ];
__device__ float g_Yf[4*SZ];                          // Y_1..Y_4 fp32
__device__ __align__(16) __nv_bfloat16 g_Ysh[5*SZ];   // Y_0..Y_4 split
__device__ __align__(16) __nv_bfloat16 g_Ysl[5*SZ];
__device__ float g_bff[20*SZ];
__device__ float g_h[32*SZ];
__device__ float g_c[32*SZ];

struct SrcPtrs { const float* p[25]; };

// ---------------- helpers -----------------------------------------------------
#define SWZ(x) ((x) ^ (((x) >> 3) & 0x70))

__device__ __forceinline__ uint32_t smem_u32(const void* p) {
  uint32_t a;
  asm("{ .reg .u64 t; cvta.to.shared.u64 t, %1; cvt.u32.u64 %0, t; }"
      : "=r"(a) : "l"(p));
  return a;
}

__device__ __forceinline__ void cpa16(uint32_t dst, const void* src) {
  asm volatile("cp.async.cg.shared.global [%0], [%1], 16;"
               :: "r"(dst), "l"(src) : "memory");
}
#define CP_COMMIT() asm volatile("cp.async.commit_group;" ::: "memory")
#define CP_WAIT(n)  asm volatile("cp.async.wait_group %0;" :: "n"(n) : "memory")

__device__ __forceinline__ void ldm4(uint32_t* r, uint32_t addr) {
  asm volatile("ldmatrix.sync.aligned.m8n8.x4.shared.b16 {%0,%1,%2,%3}, [%4];"
               : "=r"(r[0]), "=r"(r[1]), "=r"(r[2]), "=r"(r[3]) : "r"(addr));
}

__device__ __forceinline__ void mma16816(float* c, const uint32_t* a,
                                         const uint32_t* b) {
  asm volatile(
      "mma.sync.aligned.m16n8k16.row.col.f32.bf16.bf16.f32 "
      "{%0,%1,%2,%3},{%4,%5,%6,%7},{%8,%9},{%0,%1,%2,%3};"
      : "+f"(c[0]), "+f"(c[1]), "+f"(c[2]), "+f"(c[3])
      : "r"(a[0]), "r"(a[1]), "r"(a[2]), "r"(a[3]), "r"(b[0]), "r"(b[1]));
}

// load one 64-wide K chunk of 4 matrices (Ah[TM],Al[TM],Bh[128],Bl[128])
template<int TM>
__device__ __forceinline__ void load_chunk(
    uint32_t sb, int s, int kc, int tid, int brow, int bcol,
    const __nv_bfloat16* a0, const __nv_bfloat16* a1,
    const __nv_bfloat16* b0, const __nv_bfloat16* b1)
{
  constexpr int ASTAGE = TM * 128;
  constexpr int STAGE  = 2 * ASTAGE + 32768;
  constexpr int ITER   = (2 * TM + 256) * 8 / 256;
#pragma unroll
  for (int i = 0; i < ITER; i++) {
    int idx = tid + i * 256;
    int c4 = idx & 7;
    int rowIdx = idx >> 3;
    const __nv_bfloat16* src;
    uint32_t dstbase;
    if (rowIdx < 2 * TM) {                 // compile-time uniform per i
      int mat = rowIdx / TM;
      int row = rowIdx % TM;
      src = (mat ? a1 : a0) + (ll)(brow + row) * ND + kc * 64 + c4 * 8;
      dstbase = mat * ASTAGE + SWZ(row * 128 + c4 * 16);
    } else {
      int rr = rowIdx - 2 * TM;
      int mat = rr >> 7;
      int row = rr & 127;
      src = (mat ? b1 : b0) + (ll)(bcol + row) * ND + kc * 64 + c4 * 8;
      dstbase = 2 * ASTAGE + mat * 16384 + SWZ(row * 128 + c4 * 16);
    }
    cpa16(sb + s * STAGE + dstbase, src);
  }
}

// ---------------- tensor-core GEMM: C = alpha*A@B~^T + beta*Cin --------------
// A,B fp32-as-split-bf16 (hi+lo). B~ is [N,K] K-major (pass B^T; symmetric ops
// pass B). offA = sAz*z + sAdiv*(z/adiv); offB = sBz*z + sBmod*(z%bmod)
// cinmode: 0 none, 1 identity (+beta on diagonal), 2 pointer
template<int TM>
__global__ __launch_bounds__(256, 1) void tc_gemm(
    const __nv_bfloat16* __restrict__ Ah, const __nv_bfloat16* __restrict__ Al,
    const __nv_bfloat16* __restrict__ Bh, const __nv_bfloat16* __restrict__ Bl,
    const float* __restrict__ Cin, float* __restrict__ Cout,
    ll sAz, ll sAdiv, int adiv,
    ll sBz, ll sBmod, int bmod,
    ll sCinz, ll sCz, float alpha, float beta, int cinmode)
{
  extern __shared__ char dsm[];
  constexpr int ASTAGE = TM * 128;
  constexpr int STAGE  = 2 * ASTAGE + 32768;
  constexpr int NI = (TM == 128) ? 8 : 4;
  constexpr int NJ = NI / 2;

  int z = blockIdx.z;
  ll offA = sAz * z + sAdiv * (z / adiv);
  ll offB = sBz * z + sBmod * (z % bmod);
  const __nv_bfloat16* ah = Ah + offA;
  const __nv_bfloat16* al = Al + offA;
  const __nv_bfloat16* bh = Bh + offB;
  const __nv_bfloat16* bl = Bl + offB;
  const int brow = blockIdx.y * TM;
  const int bcol = blockIdx.x * 128;

  int tid = threadIdx.x;
  int lane = tid & 31;
  int wid = tid >> 5;
  int wrow, wcol;
  if (TM == 128) { wrow = (wid & 3) * 32; wcol = (wid >> 2) * 64; }
  else           { wrow = (wid & 1) * 32; wcol = (wid >> 1) * 32; }

  uint32_t raw = smem_u32(dsm);
  uint32_t sb = (raw + 1023) & ~1023u;

  float acc[2][NI][4];
#pragma unroll
  for (int mi = 0; mi < 2; mi++)
#pragma unroll
    for (int ni = 0; ni < NI; ni++)
#pragma unroll
      for (int e = 0; e < 4; e++) acc[mi][ni][e] = 0.0f;

  int a_r  = (lane & 7) + ((lane >> 3) & 1) * 8;
  int a_k8 = ((lane >> 4) & 1) * 8;
  int b_r  = (lane & 7) + ((lane >> 4) & 1) * 8;
  int b_k8 = ((lane >> 3) & 1) * 8;

  load_chunk<TM>(sb, 0, 0, tid, brow, bcol, ah, al, bh, bl); CP_COMMIT();
  load_chunk<TM>(sb, 1, 1, tid, brow, bcol, ah, al, bh, bl); CP_COMMIT();

  for (int kc = 0; kc < 12; kc++) {
    if (kc < 11) { CP_WAIT(1); } else { CP_WAIT(0); }
    __syncthreads();

    uint32_t st  = sb + (kc % 3) * STAGE;
    uint32_t tAh = st;
    uint32_t tAl = st + ASTAGE;
    uint32_t tBh = st + 2 * ASTAGE;
    uint32_t tBl = tBh + 16384;

#pragma unroll
    for (int s = 0; s < 4; s++) {
      uint32_t fah[2][4], fal[2][4];
#pragma unroll
      for (int mi = 0; mi < 2; mi++) {
        int r = wrow + mi * 16 + a_r;
        uint32_t off = SWZ(r * 128 + (s * 16 + a_k8) * 2);
        ldm4(fah[mi], tAh + off);
        ldm4(fal[mi], tAl + off);
      }
      uint32_t fbh[NI][2], fbl[NI][2];
#pragma unroll
      for (int nj = 0; nj < NJ; nj++) {
        int r = wcol + nj * 16 + b_r;
        uint32_t off = SWZ(r * 128 + (s * 16 + b_k8) * 2);
        uint32_t t4[4];
        ldm4(t4, tBh + off);
        fbh[nj * 2][0] = t4[0]; fbh[nj * 2][1] = t4[1];
        fbh[nj * 2 + 1][0] = t4[2]; fbh[nj * 2 + 1][1] = t4[3];
        ldm4(t4, tBl + off);
        fbl[nj * 2][0] = t4[0]; fbl[nj * 2][1] = t4[1];
        fbl[nj * 2 + 1][0] = t4[2]; fbl[nj * 2 + 1][1] = t4[3];
      }
#pragma unroll
      for (int mi = 0; mi < 2; mi++)
#pragma unroll
        for (int ni = 0; ni < NI; ni++)
          mma16816(acc[mi][ni], fah[mi], fbh[ni]);
#pragma unroll
      for (int mi = 0; mi < 2; mi++)
#pragma unroll
        for (int ni = 0; ni < NI; ni++)
          mma16816(acc[mi][ni], fah[mi], fbl[ni]);
#pragma unroll
      for (int mi = 0; mi < 2; mi++)
#pragma unroll
        for (int ni = 0; ni < NI; ni++)
          mma16816(acc[mi][ni], fal[mi], fbh[ni]);
    }

    if (kc + 2 < 12) {
      load_chunk<TM>(sb, (kc + 2) % 3, kc + 2, tid, brow, bcol, ah, al, bh, bl);
      CP_COMMIT();
    }
  }

  // ---- epilogue: registers -> gmem ------------------------------------------
  const float* cinp = (cinmode == 2) ? (Cin + sCinz * z) : (const float*)0;
  float* co = Cout + sCz * z;
  int qr = lane >> 2, qc = lane & 3;

#pragma unroll
  for (int mi = 0; mi < 2; mi++) {
#pragma unroll
    for (int ni = 0; ni < NI; ni++) {
      int gr0 = brow + wrow + mi * 16 + qr;
      int gc  = bcol + wcol + ni * 8 + qc * 2;
      float2 v0, v1;
      v0.x = alpha * acc[mi][ni][0];
      v0.y = alpha * acc[mi][ni][1];
      v1.x = alpha * acc[mi][ni][2];
      v1.y = alpha * acc[mi][ni][3];
      if (cinmode == 2) {
        float2 c0 = *(const float2*)&cinp[(ll)gr0 * ND + gc];
        float2 c1 = *(const float2*)&cinp[(ll)(gr0 + 8) * ND + gc];
        v0.x += beta * c0.x; v0.y += beta * c0.y;
        v1.x += beta * c1.x; v1.y += beta * c1.y;
      } else if (cinmode == 1) {
        if (gr0 == gc)         v0.x += beta;
        if (gr0 == gc + 1)     v0.y += beta;
        if (gr0 + 8 == gc)     v1.x += beta;
        if (gr0 + 8 == gc + 1) v1.y += beta;
      }
      *(float2*)&co[(ll)gr0 * ND + gc]       = v0;
      *(float2*)&co[(ll)(gr0 + 8) * ND + gc] = v1;
    }
  }
}

// ---------------- fp32 -> split bf16 -----------------------------------------
__device__ __forceinline__ uint32_t pack2(__nv_bfloat16 a, __nv_bfloat16 b) {
  __nv_bfloat162 t(a, b);
  return *reinterpret_cast<uint32_t*>(&t);
}

__global__ __launch_bounds__(256) void split_kernel(
    const float* __restrict__ src, __nv_bfloat16* __restrict__ hi,
    __nv_bfloat16* __restrict__ lo, ll sS, ll sD)
{
  ll so = sS * blockIdx.z, dofs = sD * blockIdx.z;
  int idx = blockIdx.x * 256 + threadIdx.x;
  float4 v = *(const float4*)(src + so + (ll)idx * 4);
  float a[4] = {v.x, v.y, v.z, v.w};
  __nv_bfloat16 h[4], l[4];
#pragma unroll
  for (int e = 0; e < 4; e++) {
    h[e] = __float2bfloat16(a[e]);
    l[e] = __float2bfloat16(a[e] - __bfloat162float(h[e]));
  }
  uint2 uh, ul;
  uh.x = pack2(h[0], h[1]); uh.y = pack2(h[2], h[3]);
  ul.x = pack2(l[0], l[1]); ul.y = pack2(l[2], l[3]);
  *(uint2*)(hi + dofs + (ll)idx * 4) = uh;
  *(uint2*)(lo + dofs + (ll)idx * 4) = ul;
}

// ---------------- transpose + split: xT = x^T --------------------------------
__global__ void tsplit_kernel(const float* __restrict__ src,
                              __nv_bfloat16* __restrict__ th,
                              __nv_bfloat16* __restrict__ tl)
{
  __shared__ float t[32][33];
  int bx = blockIdx.x * 32, by = blockIdx.y * 32;
  int tx = threadIdx.x, ty = threadIdx.y;
#pragma unroll
  for (int i = 0; i < 4; i++)
    t[ty + 8 * i][tx] = src[(ll)(by + ty + 8 * i) * ND + bx + tx];
  __syncthreads();
#pragma unroll
  for (int i = 0; i < 4; i++) {
    float a = t[tx][ty + 8 * i];
    __nv_bfloat16 h = __float2bfloat16(a);
    __nv_bfloat16 l = __float2bfloat16(a - __bfloat162float(h));
    ll o = (ll)(bx + ty + 8 * i) * ND + by + tx;
    th[o] = h;
    tl[o] = l;
  }
}

// ---------------- fused conv-combine + LSTM gates + dx -----------------------
__device__ __forceinline__ float sigf(float v) {
  return __fdividef(1.0f, 1.0f + __expf(-v));
}

__global__ __launch_bounds__(256) void fused_rnn(
    SrcPtrs srcs, const float* __restrict__ theta, const float* __restrict__ bias,
    const float* __restrict__ Wf, const float* __restrict__ Uf, const float* __restrict__ bf_,
    const float* __restrict__ Wi, const float* __restrict__ Ui, const float* __restrict__ bi_,
    const float* __restrict__ Wo, const float* __restrict__ Uo, const float* __restrict__ bo_,
    const float* __restrict__ Wc, const float* __restrict__ Uc, const float* __restrict__ bc_,
    const float* __restrict__ Wout, const float* __restrict__ bout,
    float* h, float* c, float* x, int first, int last)
{
  extern __shared__ float ds[];
  float* th  = ds;           // 800
  float* bs  = ds + 800;     // 32
  float* swo = ds + 832;     // 32
  float* sbg = ds + 864;     // 128 (4 gates x 32)
  float* sW  = ds + 992;     // 4096  [k][gate][o]
  float* sU  = ds + 5088;    // 4096
  float* sxc = ds + 9184;    // 4096  [k][r]
  float* sdx = ds + 13280;   // 128*9

  int t = threadIdx.x;
  for (int i = t; i < 800; i += 256) th[i] = theta[i];
  if (t < 32) { bs[t] = bias[t]; swo[t] = Wout[t]; }
  {
    const float* Ws[4] = {Wf, Wi, Wo, Wc};
    const float* Us[4] = {Uf, Ui, Uo, Uc};
    for (int idx = t; idx < 4096; idx += 256) {
      int k = idx >> 7, g = (idx >> 5) & 3, o = idx & 31;
      sW[(k * 4 + g) * 32 + o] = Ws[g][k * 32 + o];
      if (!first) sU[(k * 4 + g) * 32 + o] = Us[g][k * 32 + o];
    }
    if (t < 128) { const float* bx[4] = {bf_, bi_, bo_, bc_}; sbg[t] = bx[t >> 5][t & 31]; }
  }
  __syncthreads();

  // ---- phase 1: conv combine -> sxc[k][r] -----------------------------------
  {
    int r  = t & 127;
    int oh = (t >> 7) * 16;
    size_t rg = (size_t)blockIdx.x * 128 + r;
    float out[16];
#pragma unroll
    for (int o = 0; o < 16; o++) out[o] = bs[oh + o];
#pragma unroll
    for (int ij = 0; ij < 25; ij++) {
      float v = __ldg(srcs.p[ij] + rg);
      const float* tw = &th[ij * 32 + oh];
#pragma unroll
      for (int o = 0; o < 16; o++) out[o] += v * tw[o];
    }
#pragma unroll
    for (int o = 0; o < 16; o++) sxc[(oh + o) * 128 + r] = out[o];
  }
  __syncthreads();

  // ---- phase 2: gate GEMM (K=32) --------------------------------------------
  int rt = t & 31, ot = t >> 5;
  size_t r0 = (size_t)blockIdx.x * 128 + rt * 4;
  int ob = ot * 4;

  float acc[4][4][4];
#pragma unroll
  for (int o = 0; o < 4; o++)
#pragma unroll
    for (int g = 0; g < 4; g++)
#pragma unroll
      for (int rr = 0; rr < 4; rr++) acc[o][g][rr] = 0.0f;

  if (first) {
#pragma unroll 4
    for (int k = 0; k < 32; k++) {
      float4 xv = *(const float4*)&sxc[k * 128 + rt * 4];
      float xr[4] = {xv.x, xv.y, xv.z, xv.w};
#pragma unroll
      for (int g = 0; g < 4; g++) {
        float4 w4 = *(const float4*)&sW[(k * 4 + g) * 32 + ob];
        float w[4] = {w4.x, w4.y, w4.z, w4.w};
#pragma unroll
        for (int o = 0; o < 4; o++)
#pragma unroll
          for (int rr = 0; rr < 4; rr++)
            acc[o][g][rr] += w[o] * xr[rr];
      }
    }
  } else {
#pragma unroll 4
    for (int k = 0; k < 32; k++) {
      float4 xv = *(const float4*)&sxc[k * 128 + rt * 4];
      float4 hv = *(const float4*)&h[(size_t)k * MNTOT + r0];
      float xr[4] = {xv.x, xv.y, xv.z, xv.w};
      float hr[4] = {hv.x, hv.y, hv.z, hv.w};
#pragma unroll
      for (int g = 0; g < 4; g++) {
        float4 w4 = *(const float4*)&sW[(k * 4 + g) * 32 + ob];
        float4 u4 = *(const float4*)&sU[(k * 4 + g) * 32 + ob];
        float w[4] = {w4.x, w4.y, w4.z, w4.w};
        float u[4] = {u4.x, u4.y, u4.z, u4.w};
#pragma unroll
        for (int o = 0; o < 4; o++)
#pragma unroll
          for (int rr = 0; rr < 4; rr++)
            acc[o][g][rr] += w[o] * xr[rr] + u[o] * hr[rr];
      }
    }
  }
  __syncthreads();   // h reads complete before in-place h writes

  // ---- phase 3: epilogue + dx partials ---------------------------------------
  float pd[4] = {0.0f, 0.0f, 0.0f, 0.0f};
#pragma unroll
  for (int o = 0; o < 4; o++) {
    int oo = ob + o;
    float co[4] = {0.0f, 0.0f, 0.0f, 0.0f};
    if (!first) {
      float4 c4 = *(const float4*)&c[(size_t)oo * MNTOT + r0];
      co[0] = c4.x; co[1] = c4.y; co[2] = c4.z; co[3] = c4.w;
    }
    float cn[4], hn[4];
#pragma unroll
    for (int rr = 0; rr < 4; rr++) {
      float ig = sigf(acc[o][1][rr] + sbg[32 + oo]);
      float cu = sigf(acc[o][3][rr] + sbg[96 + oo]);
      float cnew = ig * cu;
      if (!first) {
        float fg = sigf(acc[o][0][rr] + sbg[oo]);
        cnew += fg * co[rr];
      }
      cn[rr] = cnew;
      pd[rr] += cnew * swo[oo];
      if (!last) {
        float og = sigf(acc[o][2][rr] + sbg[64 + oo]);
        hn[rr] = og * sigf(cnew);
      }
    }
    if (!last) {
      float4 cv; cv.x = cn[0]; cv.y = cn[1]; cv.z = cn[2]; cv.w = cn[3];
      float4 hv; hv.x = hn[0]; hv.y = hn[1]; hv.z = hn[2]; hv.w = hn[3];
      *(float4*)&c[(size_t)oo * MNTOT + r0] = cv;
      *(float4*)&h[(size_t)oo * MNTOT + r0] = hv;
    }
  }
#pragma unroll
  for (int rr = 0; rr < 4; rr++)
    sdx[(rt * 4 + rr) * 9 + ot] = pd[rr];
  __syncthreads();

  if (t < 128) {
    float s = __ldg(bout);
#pragma unroll
    for (int o2 = 0; o2 < 8; o2++) s += sdx[t * 9 + o2];
    x[(size_t)blockIdx.x * 128 + t] += tanhf(s);
  }
}

// ---------------- orchestration ----------------------------------------------
extern "C" void kernel_launch(void* const* d_in, const int* in_sizes, int n_in,
                              void* d_out, int out_size)
{
  const float* x     = (const float*)d_in[0];
  const float* L_row = (const float*)d_in[1];
  const float* L_col = (const float*)d_in[2];
  const float* theta = (const float*)d_in[3];
  const float* bias  = (const float*)d_in[4];
  const float* W_f = (const float*)d_in[5];
  const float* U_f = (const float*)d_in[6];
  const float* b_f = (const float*)d_in[7];
  const float* W_i = (const float*)d_in[8];
  const float* U_i = (const float*)d_in[9];
  const float* b_i = (const float*)d_in[10];
  const float* W_o = (const float*)d_in[11];
  const float* U_o = (const float*)d_in[12];
  const float* b_o = (const float*)d_in[13];
  const float* W_c = (const float*)d_in[14];
  const float* U_c = (const float*)d_in[15];
  const float* b_c = (const float*)d_in[16];
  const float* W_out = (const float*)d_in[17];
  const float* b_out = (const float*)d_in[18];
  // d_in[19] = nb_iterations_rnn = 3 (fixed by setup)

  float* xcur = (float*)d_out;

  float *Tf, *Yf, *bff, *h, *c;
  __nv_bfloat16 *Tsh, *Tsl, *xTh, *xTl, *Ysh, *Ysl;
  cudaGetSymbolAddress((void**)&Tf,  g_Tf);
  cudaGetSymbolAddress((void**)&Tsh, g_Tsh);
  cudaGetSymbolAddress((void**)&Tsl, g_Tsl);
  cudaGetSymbolAddress((void**)&xTh, g_xTh);
  cudaGetSymbolAddress((void**)&xTl, g_xTl);
  cudaGetSymbolAddress((void**)&Yf,  g_Yf);
  cudaGetSymbolAddress((void**)&Ysh, g_Ysh);
  cudaGetSymbolAddress((void**)&Ysl, g_Ysl);
  cudaGetSymbolAddress((void**)&bff, g_bff);
  cudaGetSymbolAddress((void**)&h,   g_h);
  cudaGetSymbolAddress((void**)&c,   g_c);

  const ll S = SZ;
  const int DSM128 = 1024 + 3 * 65536;   // 3-stage, TM=128
  const int DSM64  = 1024 + 3 * 49152;   // 3-stage, TM=64
  const int FSM    = (800 + 32 + 32 + 128 + 4096 * 3 + 128 * 9) * 4;
  cudaFuncSetAttribute(tc_gemm<128>, cudaFuncAttributeMaxDynamicSharedMemorySize, DSM128);
  cudaFuncSetAttribute(tc_gemm<64>,  cudaFuncAttributeMaxDynamicSharedMemorySize, DSM64);
  cudaFuncSetAttribute(fused_rnn,    cudaFuncAttributeMaxDynamicSharedMemorySize, FSM);

  cudaMemcpyAsync(xcur, x, SZ * sizeof(float), cudaMemcpyDeviceToDevice);
  cudaMemcpyAsync(Tf + 1 * S, L_row, SZ * sizeof(float), cudaMemcpyDeviceToDevice);
  cudaMemcpyAsync(Tf + 6 * S, L_col, SZ * sizeof(float), cudaMemcpyDeviceToDevice);
  {
    dim3 g(SZ / 1024, 1, 2);
    split_kernel<<<g, 256>>>(Tf + S, Tsh + S, Tsl + S, 5 * S, 5 * S);
  }

  // Chebyshev: T_k = 2*L@T_{k-1} - T_{k-2} (symmetric operands); TM=64 fills chip
  for (int k = 2; k <= 4; k++) {
    dim3 g(6, 12, 2);
    int cinmode = (k == 2) ? 1 : 2;
    const float* cin = (k == 2) ? (const float*)0 : (Tf + (ll)(k - 2) * S);
    tc_gemm<64><<<g, 256, DSM64>>>(
        Tsh + S, Tsl + S,
        Tsh + (ll)(k - 1) * S, Tsl + (ll)(k - 1) * S,
        cin, Tf + (ll)k * S,
        5 * S, 0, 1,
        5 * S, 0, 1,
        5 * S, 5 * S, 2.0f, -1.0f, cinmode);
    dim3 gs(SZ / 1024, 1, 2);
    split_kernel<<<gs, 256>>>(Tf + (ll)k * S, Tsh + (ll)k * S, Tsl + (ll)k * S,
                              5 * S, 5 * S);
  }

  SrcPtrs sp;
  for (int i = 0; i < 5; i++)
    for (int j = 0; j < 5; j++)
      sp.p[i * 5 + j] = (j == 0)
          ? ((i == 0) ? (const float*)xcur : (Yf + (ll)(i - 1) * S))
          : (bff + (ll)(i * 4 + j - 1) * S);

  for (int it = 0; it < 3; it++) {
    {
      dim3 g(24, 24);
      dim3 b(32, 8);
      tsplit_kernel<<<g, b>>>(xcur, xTh, xTl);
    }
    {
      dim3 g(SZ / 1024, 1, 1);
      split_kernel<<<g, 256>>>(xcur, Ysh, Ysl, 0, 0);
    }
    // Y_z+1 = Tr_{1+z} @ x   (B~ = x^T), z = 0..3
    {
      dim3 g(6, 6, 4);
      tc_gemm<128><<<g, 256, DSM128>>>(
          Tsh + S, Tsl + S, xTh, xTl,
          (const float*)0, Yf,
          S, 0, 1,    0, 0, 1,
          0, S, 1.0f, 0.0f, 0);
    }
    {
      dim3 g(SZ / 1024, 1, 4);
      split_kernel<<<g, 256>>>(Yf, Ysh + S, Ysl + S, S, S);
    }
    // bf[z] = Y_{z/4} @ Tc_{1+z%4}  (B~ = Tc symmetric), z = 0..19
    {
      dim3 g(6, 6, 20);
      tc_gemm<128><<<g, 256, DSM128>>>(
          Ysh, Ysl, Tsh + 6 * S, Tsl + 6 * S,
          (const float*)0, bff,
          0, S, 4,    0, S, 4,
          0, S, 1.0f, 0.0f, 0);
    }
    fused_rnn<<<SZ / 128, 256, FSM>>>(
        sp, theta, bias,
        W_f, U_f, b_f, W_i, U_i, b_i, W_o, U_o, b_o, W_c, U_c, b_c,
        W_out, b_out, h, c, xcur, (it == 0) ? 1 : 0, (it == 2) ? 1 : 0);
  }
}